// round 1
// baseline (speedup 1.0000x reference)
#include <cuda_runtime.h>
#include <math.h>

// Problem constants (fixed shapes per reference)
#define NROWS  4096          // B*L anchors
#define DDIM   256           // embedding dim
#define KMEM   16384         // memory queue rows
#define ZCOLS  4096          // z-part of the logit columns
#define NCOLS  20480         // total logit columns (ZCOLS + KMEM)
#define LSEQ   256           // L
#define SPLITS 9             // column splits (160 col tiles distributed 18/18/.../17/17)
#define TM     128           // rows per block
#define TN     128           // cols per tile
#define BS_STRIDE 66         // Bs row stride (words) -> conflict-free LDS.64
#define INV_T  (1.0f/0.07f)
#define NEG_BIG (-1.0e30f)

// Scratch (no allocations allowed)
__device__ float g_pm[SPLITS * NROWS];
__device__ float g_ps[SPLITS * NROWS];
__device__ float g_pp[NROWS];

// ---------------------------------------------------------------------------
// Main fused GEMM + online logsumexp kernel.
// Block: 256 threads = 16x16 thread grid, each thread owns an 8x8 micro-tile.
// Rows:  m0 + ty*8 + i   (contiguous 8 rows per thread, broadcast across tx)
// Cols:  c0 + tx + 16*j  (strided micro-tile -> conflict-free Bs reads)
// ---------------------------------------------------------------------------
__global__ __launch_bounds__(256, 1)
void lse_main(const float* __restrict__ z, const float* __restrict__ mem) {
    extern __shared__ float smem[];
    float* As = smem;                 // [TM][DDIM]  = 128 KB, resident all tiles
    float* Bs = smem + TM * DDIM;     // [TN][BS_STRIDE] = 33 KB, per 64-k chunk

    const int tid = threadIdx.x;
    const int tx  = tid & 15;
    const int ty  = tid >> 4;
    const int m0  = blockIdx.x * TM;
    const int s   = blockIdx.y;

    // column-tile range for this split: 160 tiles over 9 splits (7x18 + 2x17)
    const int lo = s * 17 + (s < 7 ? s : 7);
    const int hi = lo + (s < 7 ? 18 : 17);

    // ---- load full A tile (Z rows m0..m0+127, all 256 k) into SMEM ----
    #pragma unroll 4
    for (int it = 0; it < 32; ++it) {
        int idx = it * 256 + tid;                 // float4 index, 0..8191
        int m   = idx >> 6;                       // /64
        int kq  = idx & 63;
        float4 v = *(const float4*)(z + (size_t)(m0 + m) * DDIM + kq * 4);
        *(float4*)(As + m * DDIM + kq * 4) = v;
    }

    // running online-softmax state per owned row
    float rm[8], rs[8];
    #pragma unroll
    for (int i = 0; i < 8; ++i) { rm[i] = NEG_BIG; rs[i] = 0.0f; }

    for (int t = lo; t < hi; ++t) {
        const int  c0    = t * TN;
        const bool zpart = (c0 < ZCOLS);
        const float* src = zpart ? z : mem;
        const int  wrow0 = zpart ? c0 : (c0 - ZCOLS);

        float acc[8][8];
        #pragma unroll
        for (int i = 0; i < 8; ++i)
            #pragma unroll
            for (int j = 0; j < 8; ++j) acc[i][j] = 0.0f;

        // K loop in 4 chunks of 64
        for (int kc = 0; kc < 4; ++kc) {
            __syncthreads();  // covers initial A load + protects Bs reuse
            // load B chunk: rows c0..c0+127 of W, k in [kc*64, kc*64+64)
            #pragma unroll
            for (int it = 0; it < 8; ++it) {
                int idx = it * 256 + tid;          // 0..2047 (float4 units)
                int c   = idx >> 4;                // /16
                int kq  = idx & 15;
                float4 v = *(const float4*)(src + (size_t)(wrow0 + c) * DDIM
                                            + kc * 64 + kq * 4);
                float* d = Bs + c * BS_STRIDE + kq * 4;
                *(float2*)(d)     = make_float2(v.x, v.y);
                *(float2*)(d + 2) = make_float2(v.z, v.w);
            }
            __syncthreads();

            const float* Ab = As + (ty * 8) * DDIM + kc * 64;
            const float* Bb = Bs + tx * BS_STRIDE;
            #pragma unroll 4
            for (int k2 = 0; k2 < 32; ++k2) {
                float2 a[8], b[8];
                #pragma unroll
                for (int i = 0; i < 8; ++i)
                    a[i] = *(const float2*)(Ab + i * DDIM + k2 * 2);
                #pragma unroll
                for (int j = 0; j < 8; ++j)
                    b[j] = *(const float2*)(Bb + j * 16 * BS_STRIDE + k2 * 2);
                #pragma unroll
                for (int i = 0; i < 8; ++i)
                    #pragma unroll
                    for (int j = 0; j < 8; ++j)
                        acc[i][j] = fmaf(a[i].y, b[j].y,
                                    fmaf(a[i].x, b[j].x, acc[i][j]));
            }
        }

        // ---- epilogue: scale, mask self, butterfly max/sum-exp, online merge
        const bool diag = zpart && (c0 == m0);
        #pragma unroll
        for (int i = 0; i < 8; ++i) {
            float v[8];
            #pragma unroll
            for (int j = 0; j < 8; ++j) v[j] = acc[i][j] * INV_T;
            if (diag) {
                const int grow = m0 + ty * 8 + i;
                #pragma unroll
                for (int j = 0; j < 8; ++j)
                    if (c0 + tx + 16 * j == grow) v[j] = NEG_BIG;
            }
            float M = v[0];
            #pragma unroll
            for (int j = 1; j < 8; ++j) M = fmaxf(M, v[j]);
            #pragma unroll
            for (int o = 1; o < 16; o <<= 1)
                M = fmaxf(M, __shfl_xor_sync(0xffffffffu, M, o));
            float S = 0.0f;
            #pragma unroll
            for (int j = 0; j < 8; ++j) S += __expf(v[j] - M);
            #pragma unroll
            for (int o = 1; o < 16; o <<= 1)
                S += __shfl_xor_sync(0xffffffffu, S, o);
            // merge (M,S) into running (rm,rs)
            const float mo = rm[i];
            const float mn = fmaxf(mo, M);
            rs[i] = rs[i] * __expf(mo - mn) + S * __expf(M - mn);
            rm[i] = mn;
        }
    }

    // write per-split partials (all tx lanes identical; lane tx==0 writes)
    if (tx == 0) {
        #pragma unroll
        for (int i = 0; i < 8; ++i) {
            const int r = m0 + ty * 8 + i;
            g_pm[s * NROWS + r] = rm[i];
            g_ps[s * NROWS + r] = rs[i];
        }
    }
}

// ---------------------------------------------------------------------------
// Combine split partials into lse, compute positive sim, per-pair term.
// ---------------------------------------------------------------------------
__global__ void lse_finalize(const float* __restrict__ z) {
    const int i = blockIdx.x * blockDim.x + threadIdx.x;
    if (i >= NROWS) return;

    float m = g_pm[i];
    #pragma unroll
    for (int s2 = 1; s2 < SPLITS; ++s2)
        m = fmaxf(m, g_pm[s2 * NROWS + i]);
    float ss = 0.0f;
    #pragma unroll
    for (int s2 = 0; s2 < SPLITS; ++s2)
        ss += g_ps[s2 * NROWS + i] * __expf(g_pm[s2 * NROWS + i] - m);
    const float lse = m + logf(ss);

    const bool valid = (i < NROWS - 1) && ((i & (LSEQ - 1)) != (LSEQ - 1));
    float pp = 0.0f;
    if (valid) {
        const float4* a = (const float4*)(z + (size_t)i * DDIM);
        const float4* b = (const float4*)(z + (size_t)(i + 1) * DDIM);
        float d0 = 0.0f;
        #pragma unroll 8
        for (int k = 0; k < DDIM / 4; ++k) {
            float4 x = a[k], y = b[k];
            d0 = fmaf(x.x, y.x, d0);
            d0 = fmaf(x.y, y.y, d0);
            d0 = fmaf(x.z, y.z, d0);
            d0 = fmaf(x.w, y.w, d0);
        }
        pp = lse - d0 * INV_T;
    }
    g_pp[i] = pp;
}

// ---------------------------------------------------------------------------
// Deterministic tree reduction to the final scalar loss.
// ---------------------------------------------------------------------------
__global__ void lse_reduce(float* __restrict__ out) {
    __shared__ float sh[256];
    const int tid = threadIdx.x;
    float v = 0.0f;
    for (int i = tid; i < NROWS; i += 256) v += g_pp[i];
    sh[tid] = v;
    __syncthreads();
    for (int o = 128; o > 0; o >>= 1) {
        if (tid < o) sh[tid] += sh[tid + o];
        __syncthreads();
    }
    if (tid == 0) out[0] = sh[0] * (1.0f / 4080.0f);  // B*(L-1) valid pairs
}

// ---------------------------------------------------------------------------
extern "C" void kernel_launch(void* const* d_in, const int* in_sizes, int n_in,
                              void* d_out, int out_size) {
    const float* z   = nullptr;
    const float* mem = nullptr;
    for (int i = 0; i < n_in; ++i) {
        if (in_sizes[i] == NROWS * DDIM && !z)  z   = (const float*)d_in[i];
        if (in_sizes[i] == KMEM * DDIM  && !mem) mem = (const float*)d_in[i];
    }
    if (!z)   z   = (const float*)d_in[0];
    if (!mem) mem = (const float*)d_in[2];

    const int smem_bytes = (TM * DDIM + TN * BS_STRIDE) * (int)sizeof(float);
    cudaFuncSetAttribute(lse_main, cudaFuncAttributeMaxDynamicSharedMemorySize,
                         smem_bytes);

    lse_main<<<dim3(32, SPLITS), 256, smem_bytes>>>(z, mem);
    lse_finalize<<<32, 128>>>(z);
    lse_reduce<<<1, 256>>>((float*)d_out);
}

// round 3
// speedup vs baseline: 3.9789x; 3.9789x over previous
#include <cuda_runtime.h>
#include <math.h>
#include <stdint.h>

// ---------------- problem constants ----------------
#define NROWS  4096          // B*L anchors
#define DDIM   256           // embedding dim
#define KMEM   16384
#define ZCOLS  4096
#define LSEQ   256
#define SPLITS 9             // 80 col tiles (width 256): 8 splits x9 + 1 x8
#define TMR    128           // rows per CTA
#define TNC    256           // cols per tile
#define SA     260           // A smem stride (floats); 260%32==4 -> conflict-free
#define SB     36            // B smem stride (floats); 36%32==4  -> conflict-free
#define INV_T  (1.0f/0.07f)
#define LOG2E  1.4426950408889634f
#define LN2F   0.6931471805599453f
#define NEG_BIG (-1.0e30f)

#define SMEM_DYN ((TMR*SA + 2*256*SB) * 4)   // 206,848 B

// ---------------- scratch (no allocations allowed) ----------------
__device__ float g_pm[SPLITS * NROWS];
__device__ float g_ps[SPLITS * NROWS];
__device__ float g_pp[NROWS];

// ---------------- helpers ----------------
__device__ __forceinline__ uint32_t f2tf(float x) {
    uint32_t r; asm("cvt.rna.tf32.f32 %0, %1;" : "=r"(r) : "f"(x)); return r;
}
__device__ __forceinline__ float ex2f(float x) {
    float r; asm("ex2.approx.f32 %0, %1;" : "=f"(r) : "f"(x)); return r;
}
__device__ __forceinline__ void mma8(float* d,
                                     uint32_t a0, uint32_t a1, uint32_t a2, uint32_t a3,
                                     uint32_t b0, uint32_t b1) {
    asm volatile(
        "mma.sync.aligned.m16n8k8.row.col.f32.tf32.tf32.f32 "
        "{%0,%1,%2,%3}, {%4,%5,%6,%7}, {%8,%9}, {%0,%1,%2,%3};"
        : "+f"(d[0]), "+f"(d[1]), "+f"(d[2]), "+f"(d[3])
        : "r"(a0), "r"(a1), "r"(a2), "r"(a3), "r"(b0), "r"(b1));
}
__device__ __forceinline__ uint32_t smem_u32(const void* p) {
    uint32_t a;
    asm("{ .reg .u64 t; cvta.to.shared.u64 t, %1; cvt.u32.u64 %0, t; }"
        : "=r"(a) : "l"(p));
    return a;
}
__device__ __forceinline__ void cp16(uint32_t dst, const void* src) {
    asm volatile("cp.async.cg.shared.global [%0], [%1], 16;" :: "r"(dst), "l"(src));
}

// ---------------------------------------------------------------------------
// Fused tf32 mma.sync GEMM + online logsumexp.
// 256 threads = 8 warps in a 2(M) x 4(N) grid; warp tile 64x64 (m16n8k8).
// A tile (128x256, tf32) resident in SMEM; B streamed in 32-k chunks via
// cp.async double buffer (raw f32, cvt.rna at fragment load).
// ---------------------------------------------------------------------------
__global__ __launch_bounds__(256, 1)
void lse_mma(const float* __restrict__ z, const float* __restrict__ mem) {
    extern __shared__ uint32_t sm[];
    __shared__ float red_m[8][64];
    __shared__ float red_s[8][64];
    uint32_t* As = sm;                  // [128][SA] tf32
    uint32_t* Bs = sm + TMR * SA;       // 2 x [256][SB] raw f32 bits

    const int tid  = threadIdx.x;
    const int wid  = tid >> 5;
    const int lane = tid & 31;
    const int wm   = wid >> 2;          // 0..1 (M)
    const int wn   = wid & 3;           // 0..3 (N)
    const int qr   = lane >> 2;         // 0..7
    const int qc   = lane & 3;          // 0..3
    const int m0   = blockIdx.x * TMR;
    const int s    = blockIdx.y;
    const int lo   = s * 9;
    const int nt   = (s < 8) ? 9 : 8;

    // ---- load + convert A tile once ----
    #pragma unroll 4
    for (int it = 0; it < 32; ++it) {
        int idx = it * 256 + tid;               // float4 index
        int m   = idx >> 6;
        int kq  = (idx & 63) << 2;
        float4 v = *(const float4*)(z + (size_t)(m0 + m) * DDIM + kq);
        uint32_t* d = As + m * SA + kq;
        d[0] = f2tf(v.x); d[1] = f2tf(v.y); d[2] = f2tf(v.z); d[3] = f2tf(v.w);
    }
    __syncthreads();

    float rm[8], rs[8];
    #pragma unroll
    for (int i = 0; i < 8; ++i) { rm[i] = NEG_BIG; rs[i] = 0.0f; }

    const uint32_t bs_base = smem_u32(Bs);
    const float Cs = INV_T * LOG2E;

    #pragma unroll 1
    for (int ti = 0; ti < nt; ++ti) {
        const int  t   = lo + ti;
        const int  c0  = t * TNC;
        const bool zp  = (c0 < ZCOLS);
        const float* src = zp ? z : mem;
        const int  w0  = zp ? c0 : (c0 - ZCOLS);

        float acc[4][8][4];
        #pragma unroll
        for (int a = 0; a < 4; ++a)
            #pragma unroll
            for (int b = 0; b < 8; ++b)
                #pragma unroll
                for (int c = 0; c < 4; ++c) acc[a][b][c] = 0.0f;

        // prologue: chunk 0 -> buf 0
        #pragma unroll
        for (int it = 0; it < 8; ++it) {
            int idx = it * 256 + tid;           // f4 idx within 256x32 chunk
            int n   = idx >> 3;
            int kq  = (idx & 7) << 2;
            cp16(bs_base + (uint32_t)((n * SB + kq) << 2),
                 src + (size_t)(w0 + n) * DDIM + kq);
        }
        asm volatile("cp.async.commit_group;" ::: "memory");

        #pragma unroll 1
        for (int kc = 0; kc < 8; ++kc) {
            const int cur = kc & 1;
            if (kc < 7) {
                const int nb = 1 - cur;
                #pragma unroll
                for (int it = 0; it < 8; ++it) {
                    int idx = it * 256 + tid;
                    int n   = idx >> 3;
                    int kq  = (idx & 7) << 2;
                    cp16(bs_base + (uint32_t)((((nb << 8) + n) * SB + kq) << 2),
                         src + (size_t)(w0 + n) * DDIM + (kc + 1) * 32 + kq);
                }
                asm volatile("cp.async.commit_group;" ::: "memory");
                asm volatile("cp.async.wait_group 1;" ::: "memory");
            } else {
                asm volatile("cp.async.wait_group 0;" ::: "memory");
            }
            __syncthreads();

            const uint32_t* Bc = Bs + cur * 256 * SB;
            #pragma unroll
            for (int ks = 0; ks < 4; ++ks) {
                const int ak = kc * 32 + ks * 8 + qc;
                uint32_t af[4][4];
                #pragma unroll
                for (int mi = 0; mi < 4; ++mi) {
                    const int r = wm * 64 + mi * 16 + qr;
                    af[mi][0] = As[r * SA + ak];
                    af[mi][1] = As[(r + 8) * SA + ak];
                    af[mi][2] = As[r * SA + ak + 4];
                    af[mi][3] = As[(r + 8) * SA + ak + 4];
                }
                uint32_t bf[8][2];
                #pragma unroll
                for (int ni = 0; ni < 8; ++ni) {
                    const int n = wn * 64 + ni * 8 + qr;
                    bf[ni][0] = f2tf(__uint_as_float(Bc[n * SB + ks * 8 + qc]));
                    bf[ni][1] = f2tf(__uint_as_float(Bc[n * SB + ks * 8 + qc + 4]));
                }
                #pragma unroll
                for (int mi = 0; mi < 4; ++mi)
                    #pragma unroll
                    for (int ni = 0; ni < 8; ++ni)
                        mma8(acc[mi][ni], af[mi][0], af[mi][1], af[mi][2], af[mi][3],
                             bf[ni][0], bf[ni][1]);
            }
            __syncthreads();
        }

        // ---- flash-LSE epilogue on register accumulators ----
        const bool dflag = zp && (c0 == (m0 & ~(TNC - 1)));
        #pragma unroll
        for (int mi = 0; mi < 4; ++mi) {
            #pragma unroll
            for (int h = 0; h < 2; ++h) {
                const int lr   = wm * 64 + mi * 16 + h * 8 + qr;  // 0..127
                const int grow = m0 + lr;
                float v[16];
                float mx = NEG_BIG;
                #pragma unroll
                for (int ni = 0; ni < 8; ++ni) {
                    #pragma unroll
                    for (int c = 0; c < 2; ++c) {
                        float x = acc[mi][ni][h * 2 + c] * Cs;
                        if (dflag) {
                            const int gcol = c0 + wn * 64 + ni * 8 + 2 * qc + c;
                            if (gcol == grow) x = NEG_BIG;
                        }
                        v[ni * 2 + c] = x;
                        mx = fmaxf(mx, x);
                    }
                }
                mx = fmaxf(mx, __shfl_xor_sync(0xffffffffu, mx, 1));
                mx = fmaxf(mx, __shfl_xor_sync(0xffffffffu, mx, 2));
                float sc = 0.0f;
                #pragma unroll
                for (int j = 0; j < 16; ++j) sc += ex2f(v[j] - mx);
                sc += __shfl_xor_sync(0xffffffffu, sc, 1);
                sc += __shfl_xor_sync(0xffffffffu, sc, 2);
                const int ri = mi * 2 + h;
                const float mn = fmaxf(rm[ri], mx);
                rs[ri] = rs[ri] * ex2f(rm[ri] - mn) + sc * ex2f(mx - mn);
                rm[ri] = mn;
            }
        }
    }

    // ---- cross-warp (N-dim) merge via smem ----
    if (qc == 0) {
        #pragma unroll
        for (int mi = 0; mi < 4; ++mi)
            #pragma unroll
            for (int h = 0; h < 2; ++h) {
                const int lrw = mi * 16 + h * 8 + qr;   // 0..63
                red_m[wid][lrw] = rm[mi * 2 + h];
                red_s[wid][lrw] = rs[mi * 2 + h];
            }
    }
    __syncthreads();
    if (tid < 128) {
        const int wmm = tid >> 6, ri = tid & 63;
        float m = red_m[wmm * 4][ri];
        #pragma unroll
        for (int w = 1; w < 4; ++w) m = fmaxf(m, red_m[wmm * 4 + w][ri]);
        float ss = 0.0f;
        #pragma unroll
        for (int w = 0; w < 4; ++w)
            ss += red_s[wmm * 4 + w][ri] * ex2f(red_m[wmm * 4 + w][ri] - m);
        g_pm[s * NROWS + m0 + tid] = m;
        g_ps[s * NROWS + m0 + tid] = ss;
    }
}

// ---------------------------------------------------------------------------
// Combine split partials (log2 domain) -> lse, positive sim, per-pair term.
// ---------------------------------------------------------------------------
__global__ void lse_finalize(const float* __restrict__ z) {
    const int i = blockIdx.x * blockDim.x + threadIdx.x;
    if (i >= NROWS) return;

    float m = g_pm[i];
    #pragma unroll
    for (int s2 = 1; s2 < SPLITS; ++s2)
        m = fmaxf(m, g_pm[s2 * NROWS + i]);
    float ss = 0.0f;
    #pragma unroll
    for (int s2 = 0; s2 < SPLITS; ++s2)
        ss += g_ps[s2 * NROWS + i] * ex2f(g_pm[s2 * NROWS + i] - m);
    const float lse = (m + log2f(ss)) * LN2F;

    const bool valid = (i < NROWS - 1) && ((i & (LSEQ - 1)) != (LSEQ - 1));
    float pp = 0.0f;
    if (valid) {
        const float4* a = (const float4*)(z + (size_t)i * DDIM);
        const float4* b = (const float4*)(z + (size_t)(i + 1) * DDIM);
        float d0 = 0.0f;
        #pragma unroll 8
        for (int k = 0; k < DDIM / 4; ++k) {
            float4 x = a[k], y = b[k];
            d0 = fmaf(x.x, y.x, d0);
            d0 = fmaf(x.y, y.y, d0);
            d0 = fmaf(x.z, y.z, d0);
            d0 = fmaf(x.w, y.w, d0);
        }
        pp = lse - d0 * INV_T;
    }
    g_pp[i] = pp;
}

__global__ void lse_reduce(float* __restrict__ out) {
    __shared__ float sh[256];
    const int tid = threadIdx.x;
    float v = 0.0f;
    for (int i = tid; i < NROWS; i += 256) v += g_pp[i];
    sh[tid] = v;
    __syncthreads();
    for (int o = 128; o > 0; o >>= 1) {
        if (tid < o) sh[tid] += sh[tid + o];
        __syncthreads();
    }
    if (tid == 0) out[0] = sh[0] * (1.0f / 4080.0f);
}

// ---------------------------------------------------------------------------
extern "C" void kernel_launch(void* const* d_in, const int* in_sizes, int n_in,
                              void* d_out, int out_size) {
    const float* z   = nullptr;
    const float* mem = nullptr;
    for (int i = 0; i < n_in; ++i) {
        if (in_sizes[i] == NROWS * DDIM && !z)   z   = (const float*)d_in[i];
        if (in_sizes[i] == KMEM * DDIM  && !mem) mem = (const float*)d_in[i];
    }
    if (!z)   z   = (const float*)d_in[0];
    if (!mem) mem = (const float*)d_in[2];

    cudaFuncSetAttribute(lse_mma, cudaFuncAttributeMaxDynamicSharedMemorySize,
                         SMEM_DYN);
    lse_mma<<<dim3(32, SPLITS), 256, SMEM_DYN>>>(z, mem);
    lse_finalize<<<32, 128>>>(z);
    lse_reduce<<<1, 256>>>((float*)d_out);
}

// round 4
// speedup vs baseline: 4.1008x; 1.0306x over previous
#include <cuda_runtime.h>
#include <math.h>
#include <stdint.h>

// ---------------- problem constants ----------------
#define NROWS  4096          // B*L anchors
#define DDIM   256           // embedding dim
#define KMEM   16384
#define ZCOLS  4096
#define WROWS  (ZCOLS + KMEM)   // 20480 rows in the fused weight matrix
#define LSEQ   256
#define SPLITS 9             // 80 col tiles (width 256): 8 splits x9 + 1 x8
#define TMR    128           // rows per CTA
#define TNC    256           // cols per tile
#define SA     264           // A smem stride (words); 264%32==8 -> conflict-free LDS.64
#define SB     40            // B smem stride (words); 40%32==8  -> conflict-free LDS.64
#define INV_T  (1.0f/0.07f)
#define LOG2E  1.4426950408889634f
#define LN2F   0.6931471805599453f
#define NEG_BIG (-1.0e30f)

#define SMEM_DYN ((TMR*SA + 2*256*SB) * 4)   // 217,088 B

// ---------------- scratch (no allocations allowed) ----------------
__device__ uint32_t g_wp[(size_t)WROWS * DDIM];   // tf32, k-pair-permuted (21 MB)
__device__ float g_pm[SPLITS * NROWS];
__device__ float g_ps[SPLITS * NROWS];
__device__ float g_pp[NROWS];

// ---------------- helpers ----------------
__device__ __forceinline__ uint32_t f2tf(float x) {
    uint32_t r; asm("cvt.rna.tf32.f32 %0, %1;" : "=r"(r) : "f"(x)); return r;
}
__device__ __forceinline__ float ex2f(float x) {
    float r; asm("ex2.approx.f32 %0, %1;" : "=f"(r) : "f"(x)); return r;
}
__device__ __forceinline__ void mma8(float* d,
                                     uint32_t a0, uint32_t a1, uint32_t a2, uint32_t a3,
                                     uint32_t b0, uint32_t b1) {
    asm volatile(
        "mma.sync.aligned.m16n8k8.row.col.f32.tf32.tf32.f32 "
        "{%0,%1,%2,%3}, {%4,%5,%6,%7}, {%8,%9}, {%0,%1,%2,%3};"
        : "+f"(d[0]), "+f"(d[1]), "+f"(d[2]), "+f"(d[3])
        : "r"(a0), "r"(a1), "r"(a2), "r"(a3), "r"(b0), "r"(b1));
}
__device__ __forceinline__ uint32_t smem_u32(const void* p) {
    uint32_t a;
    asm("{ .reg .u64 t; cvta.to.shared.u64 t, %1; cvt.u32.u64 %0, t; }"
        : "=r"(a) : "l"(p));
    return a;
}
__device__ __forceinline__ void cp16(uint32_t dst, const void* src) {
    asm volatile("cp.async.cg.shared.global [%0], [%1], 16;" :: "r"(dst), "l"(src));
}

// ---------------------------------------------------------------------------
// Pre-pass: convert z||mem to tf32, k-pair-permuted within each 8-k group:
//   row layout per group g: [k0, k4, k1, k5, k2, k6, k3, k7]
// so the mma fragment pair (k=qc, k=qc+4) sits at words (2qc, 2qc+1).
// ---------------------------------------------------------------------------
__global__ __launch_bounds__(256)
void prep(const float* __restrict__ z, const float* __restrict__ mem) {
    const int idx = blockIdx.x * 256 + threadIdx.x;    // one 8-k group each
    const int row = idx >> 5;
    const int g   = idx & 31;
    if (row >= WROWS) return;
    const float* src = (row < ZCOLS) ? (z + (size_t)row * DDIM)
                                     : (mem + (size_t)(row - ZCOLS) * DDIM);
    float4 lo = *(const float4*)(src + g * 8);
    float4 hi = *(const float4*)(src + g * 8 + 4);
    uint4 o0 = make_uint4(f2tf(lo.x), f2tf(hi.x), f2tf(lo.y), f2tf(hi.y));
    uint4 o1 = make_uint4(f2tf(lo.z), f2tf(hi.z), f2tf(lo.w), f2tf(hi.w));
    uint32_t* d = g_wp + (size_t)row * DDIM + g * 8;
    *(uint4*)(d)     = o0;
    *(uint4*)(d + 4) = o1;
}

// ---------------------------------------------------------------------------
// Fused tf32 mma.sync GEMM + online logsumexp.
// 256 threads = 8 warps in 2(M) x 4(N); warp tile 64x64.
// A tile (128x256 tf32, permuted) SMEM-resident; B streamed via cp.async
// double buffer. All fragment loads are LDS.64, zero cvt in the main loop.
// ---------------------------------------------------------------------------
__global__ __launch_bounds__(256, 1)
void lse_mma(const float* __restrict__ zdummy) {
    extern __shared__ uint32_t sm[];
    __shared__ float red_m[8][64];
    __shared__ float red_s[8][64];
    uint32_t* As = sm;                  // [128][SA]
    uint32_t* Bs = sm + TMR * SA;       // 2 x [256][SB]

    const int tid  = threadIdx.x;
    const int wid  = tid >> 5;
    const int lane = tid & 31;
    const int wm   = wid >> 2;
    const int wn   = wid & 3;
    const int qr   = lane >> 2;         // 0..7
    const int qc   = lane & 3;          // 0..3
    const int m0   = blockIdx.x * TMR;
    const int s    = blockIdx.y;
    const int lo   = s * 9;
    const int nt   = (s < 8) ? 9 : 8;

    // ---- A tile: already tf32+permuted in g_wp (z = rows 0..4095) ----
    #pragma unroll 4
    for (int it = 0; it < 32; ++it) {
        int idx = it * 256 + tid;
        int m   = idx >> 6;
        int kq  = (idx & 63) << 2;
        uint4 v = *(const uint4*)(g_wp + (size_t)(m0 + m) * DDIM + kq);
        *(uint4*)(As + m * SA + kq) = v;
    }
    __syncthreads();

    float rm[8], rs[8];
    #pragma unroll
    for (int i = 0; i < 8; ++i) { rm[i] = NEG_BIG; rs[i] = 0.0f; }

    const uint32_t bs_base = smem_u32(Bs);
    const float Cs = INV_T * LOG2E;

    // initial prologue: tile lo, chunk 0 -> buf 0
    {
        const int c0 = lo * TNC;
        #pragma unroll
        for (int it = 0; it < 8; ++it) {
            int idx = it * 256 + tid;
            int n   = idx >> 3;
            int kq  = (idx & 7) << 2;
            cp16(bs_base + (uint32_t)((n * SB + kq) << 2),
                 g_wp + (size_t)(c0 + n) * DDIM + kq);
        }
        asm volatile("cp.async.commit_group;" ::: "memory");
    }

    #pragma unroll 1
    for (int ti = 0; ti < nt; ++ti) {
        const int  c0  = (lo + ti) * TNC;
        const bool zp  = (c0 < ZCOLS);

        float acc[4][8][4];
        #pragma unroll
        for (int a = 0; a < 4; ++a)
            #pragma unroll
            for (int b = 0; b < 8; ++b)
                #pragma unroll
                for (int c = 0; c < 4; ++c) acc[a][b][c] = 0.0f;

        #pragma unroll 1
        for (int kc = 0; kc < 8; ++kc) {
            const int cur = kc & 1;
            if (kc < 7) {
                const int nb = 1 - cur;
                #pragma unroll
                for (int it = 0; it < 8; ++it) {
                    int idx = it * 256 + tid;
                    int n   = idx >> 3;
                    int kq  = (idx & 7) << 2;
                    cp16(bs_base + (uint32_t)((((nb << 8) + n) * SB + kq) << 2),
                         g_wp + (size_t)(c0 + n) * DDIM + (kc + 1) * 32 + kq);
                }
                asm volatile("cp.async.commit_group;" ::: "memory");
                asm volatile("cp.async.wait_group 1;" ::: "memory");
            } else {
                asm volatile("cp.async.wait_group 0;" ::: "memory");
            }
            __syncthreads();

            const uint32_t* Bc = Bs + cur * 256 * SB;
            #pragma unroll
            for (int ks = 0; ks < 4; ++ks) {
                const int aw = kc * 32 + ks * 8 + qc * 2;  // permuted word
                uint2 afl[4], afh[4];
                #pragma unroll
                for (int mi = 0; mi < 4; ++mi) {
                    const int r = wm * 64 + mi * 16 + qr;
                    afl[mi] = *(const uint2*)(As + r * SA + aw);
                    afh[mi] = *(const uint2*)(As + (r + 8) * SA + aw);
                }
                uint2 bf[8];
                const int bw = ks * 8 + qc * 2;
                #pragma unroll
                for (int ni = 0; ni < 8; ++ni) {
                    const int n = wn * 64 + ni * 8 + qr;
                    bf[ni] = *(const uint2*)(Bc + n * SB + bw);
                }
                #pragma unroll
                for (int mi = 0; mi < 4; ++mi)
                    #pragma unroll
                    for (int ni = 0; ni < 8; ++ni)
                        mma8(acc[mi][ni], afl[mi].x, afh[mi].x,
                             afl[mi].y, afh[mi].y, bf[ni].x, bf[ni].y);
            }
            __syncthreads();
        }

        // prefetch next tile's chunk 0 into buf 0 (hidden under the epilogue)
        if (ti + 1 < nt) {
            const int c1 = (lo + ti + 1) * TNC;
            #pragma unroll
            for (int it = 0; it < 8; ++it) {
                int idx = it * 256 + tid;
                int n   = idx >> 3;
                int kq  = (idx & 7) << 2;
                cp16(bs_base + (uint32_t)((n * SB + kq) << 2),
                     g_wp + (size_t)(c1 + n) * DDIM + kq);
            }
            asm volatile("cp.async.commit_group;" ::: "memory");
        }

        // ---- flash-LSE epilogue on register accumulators ----
        const bool dflag = zp && (c0 == (m0 & ~(TNC - 1)));
        #pragma unroll
        for (int mi = 0; mi < 4; ++mi) {
            #pragma unroll
            for (int h = 0; h < 2; ++h) {
                const int lr   = wm * 64 + mi * 16 + h * 8 + qr;
                const int grow = m0 + lr;
                float v[16];
                float mx = NEG_BIG;
                #pragma unroll
                for (int ni = 0; ni < 8; ++ni) {
                    #pragma unroll
                    for (int c = 0; c < 2; ++c) {
                        float x = acc[mi][ni][h * 2 + c] * Cs;
                        if (dflag) {
                            const int gcol = c0 + wn * 64 + ni * 8 + 2 * qc + c;
                            if (gcol == grow) x = NEG_BIG;
                        }
                        v[ni * 2 + c] = x;
                        mx = fmaxf(mx, x);
                    }
                }
                mx = fmaxf(mx, __shfl_xor_sync(0xffffffffu, mx, 1));
                mx = fmaxf(mx, __shfl_xor_sync(0xffffffffu, mx, 2));
                float sc = 0.0f;
                #pragma unroll
                for (int j = 0; j < 16; ++j) sc += ex2f(v[j] - mx);
                sc += __shfl_xor_sync(0xffffffffu, sc, 1);
                sc += __shfl_xor_sync(0xffffffffu, sc, 2);
                const int ri = mi * 2 + h;
                const float mn = fmaxf(rm[ri], mx);
                rs[ri] = rs[ri] * ex2f(rm[ri] - mn) + sc * ex2f(mx - mn);
                rm[ri] = mn;
            }
        }
    }

    // ---- cross-warp (N-dim) merge via smem ----
    if (qc == 0) {
        #pragma unroll
        for (int mi = 0; mi < 4; ++mi)
            #pragma unroll
            for (int h = 0; h < 2; ++h) {
                const int lrw = mi * 16 + h * 8 + qr;
                red_m[wid][lrw] = rm[mi * 2 + h];
                red_s[wid][lrw] = rs[mi * 2 + h];
            }
    }
    __syncthreads();
    if (tid < 128) {
        const int wmm = tid >> 6, ri = tid & 63;
        float m = red_m[wmm * 4][ri];
        #pragma unroll
        for (int w = 1; w < 4; ++w) m = fmaxf(m, red_m[wmm * 4 + w][ri]);
        float ss = 0.0f;
        #pragma unroll
        for (int w = 0; w < 4; ++w)
            ss += red_s[wmm * 4 + w][ri] * ex2f(red_m[wmm * 4 + w][ri] - m);
        g_pm[s * NROWS + m0 + tid] = m;
        g_ps[s * NROWS + m0 + tid] = ss;
    }
}

// ---------------------------------------------------------------------------
__global__ void lse_finalize(const float* __restrict__ z) {
    const int i = blockIdx.x * blockDim.x + threadIdx.x;
    if (i >= NROWS) return;

    float m = g_pm[i];
    #pragma unroll
    for (int s2 = 1; s2 < SPLITS; ++s2)
        m = fmaxf(m, g_pm[s2 * NROWS + i]);
    float ss = 0.0f;
    #pragma unroll
    for (int s2 = 0; s2 < SPLITS; ++s2)
        ss += g_ps[s2 * NROWS + i] * ex2f(g_pm[s2 * NROWS + i] - m);
    const float lse = (m + log2f(ss)) * LN2F;

    const bool valid = (i < NROWS - 1) && ((i & (LSEQ - 1)) != (LSEQ - 1));
    float pp = 0.0f;
    if (valid) {
        const float4* a = (const float4*)(z + (size_t)i * DDIM);
        const float4* b = (const float4*)(z + (size_t)(i + 1) * DDIM);
        float d0 = 0.0f;
        #pragma unroll 8
        for (int k = 0; k < DDIM / 4; ++k) {
            float4 x = a[k], y = b[k];
            d0 = fmaf(x.x, y.x, d0);
            d0 = fmaf(x.y, y.y, d0);
            d0 = fmaf(x.z, y.z, d0);
            d0 = fmaf(x.w, y.w, d0);
        }
        pp = lse - d0 * INV_T;
    }
    g_pp[i] = pp;
}

__global__ void lse_reduce(float* __restrict__ out) {
    __shared__ float sh[256];
    const int tid = threadIdx.x;
    float v = 0.0f;
    for (int i = tid; i < NROWS; i += 256) v += g_pp[i];
    sh[tid] = v;
    __syncthreads();
    for (int o = 128; o > 0; o >>= 1) {
        if (tid < o) sh[tid] += sh[tid + o];
        __syncthreads();
    }
    if (tid == 0) out[0] = sh[0] * (1.0f / 4080.0f);
}

// ---------------------------------------------------------------------------
extern "C" void kernel_launch(void* const* d_in, const int* in_sizes, int n_in,
                              void* d_out, int out_size) {
    const float* z   = nullptr;
    const float* mem = nullptr;
    for (int i = 0; i < n_in; ++i) {
        if (in_sizes[i] == NROWS * DDIM && !z)   z   = (const float*)d_in[i];
        if (in_sizes[i] == KMEM * DDIM  && !mem) mem = (const float*)d_in[i];
    }
    if (!z)   z   = (const float*)d_in[0];
    if (!mem) mem = (const float*)d_in[2];

    cudaFuncSetAttribute(lse_mma, cudaFuncAttributeMaxDynamicSharedMemorySize,
                         SMEM_DYN);
    prep<<<(WROWS * 32 + 255) / 256, 256>>>(z, mem);
    lse_mma<<<dim3(32, SPLITS), 256, SMEM_DYN>>>(z);
    lse_finalize<<<32, 128>>>(z);
    lse_reduce<<<1, 256>>>((float*)d_out);
}